// round 16
// baseline (speedup 1.0000x reference)
#include <cuda_runtime.h>
#include <cuda_bf16.h>
#include <math.h>
#include <stdint.h>

// ---------------- problem constants ----------------------------------------
#define BB   2
#define SS   1024
#define DD   1024
#define HH   16
#define DKK  64
#define FF   4096
#define LL   4
#define VV   32000
#define MM   (BB*SS)
#define LNEPS 1e-5f

// ---------------- device scratch (no allocation allowed) -------------------
__device__ float g_x  [MM*DD];
__device__ float g_qkv[3*MM*DD];       // planes: Q | K | V
__device__ float g_ao [MM*DD];
__device__ float g_y  [MM*DD];
__device__ float g_ff [MM*FF];

// ---------------- helpers ---------------------------------------------------
__device__ __forceinline__ uint32_t smem_u32(const void* p) {
    uint32_t a;
    asm("{ .reg .u64 t; cvta.to.shared.u64 t, %1; cvt.u32.u64 %0, t; }"
        : "=r"(a) : "l"(p));
    return a;
}
#define LDSM_X4(r0, r1, r2, r3, addr) \
    asm volatile("ldmatrix.sync.aligned.m8n8.x4.shared.b16 {%0,%1,%2,%3}, [%4];" \
                 : "=r"(r0), "=r"(r1), "=r"(r2), "=r"(r3) : "r"(addr))
#define LDSM_X4_T(r0, r1, r2, r3, addr) \
    asm volatile("ldmatrix.sync.aligned.m8n8.x4.trans.shared.b16 {%0,%1,%2,%3}, [%4];" \
                 : "=r"(r0), "=r"(r1), "=r"(r2), "=r"(r3) : "r"(addr))
#define MMA_BF16(c0, c1, c2, c3, a0, a1, a2, a3, b0, b1) \
    asm volatile("mma.sync.aligned.m16n8k16.row.col.f32.bf16.bf16.f32 " \
                 "{%0,%1,%2,%3}, {%4,%5,%6,%7}, {%8,%9}, {%0,%1,%2,%3};" \
                 : "+f"(c0), "+f"(c1), "+f"(c2), "+f"(c3) \
                 : "r"(a0), "r"(a1), "r"(a2), "r"(a3), "r"(b0), "r"(b1))

// split float4 -> packed hi-bf16x4 and lo-bf16x4
__device__ __forceinline__ void split4(float4 v, uint2& hi, uint2& lo) {
    uint32_t h0 = (uint32_t)__bfloat16_as_ushort(__float2bfloat16(v.x));
    uint32_t h1 = (uint32_t)__bfloat16_as_ushort(__float2bfloat16(v.y));
    uint32_t h2 = (uint32_t)__bfloat16_as_ushort(__float2bfloat16(v.z));
    uint32_t h3 = (uint32_t)__bfloat16_as_ushort(__float2bfloat16(v.w));
    hi.x = h0 | (h1 << 16);
    hi.y = h2 | (h3 << 16);
    float l0 = v.x - __uint_as_float(h0 << 16);
    float l1 = v.y - __uint_as_float(h1 << 16);
    float l2 = v.z - __uint_as_float(h2 << 16);
    float l3 = v.w - __uint_as_float(h3 << 16);
    uint32_t q0 = (uint32_t)__bfloat16_as_ushort(__float2bfloat16(l0));
    uint32_t q1 = (uint32_t)__bfloat16_as_ushort(__float2bfloat16(l1));
    uint32_t q2 = (uint32_t)__bfloat16_as_ushort(__float2bfloat16(l2));
    uint32_t q3 = (uint32_t)__bfloat16_as_ushort(__float2bfloat16(l3));
    lo.x = q0 | (q1 << 16);
    lo.y = q2 | (q3 << 16);
}

__device__ __forceinline__ uint32_t pack_bf16x2(float a, float b) {
    uint32_t ua = (uint32_t)__bfloat16_as_ushort(__float2bfloat16(a));
    uint32_t ub = (uint32_t)__bfloat16_as_ushort(__float2bfloat16(b));
    return ua | (ub << 16);
}

// ---------------- shared GEMM body (R12/R13 proven inner loop) --------------
#define SAST 40
#define TILE_ELEMS (128 * SAST)
#define GSMEM_BYTES (8 * TILE_ELEMS * 2)   // 81920 B

__device__ __forceinline__ void gemm_body(
    const float* __restrict__ A, const float* __restrict__ B,
    const float* __restrict__ bias, float* __restrict__ C,
    int M, int N, int K, int relu, int m0, int n0, char* smem_raw)
{
    __nv_bfloat16* smem = (__nv_bfloat16*)smem_raw;
    __nv_bfloat16* tAhi[2] = { smem,                  smem + 4 * TILE_ELEMS };
    __nv_bfloat16* tAlo[2] = { smem + 1 * TILE_ELEMS, smem + 5 * TILE_ELEMS };
    __nv_bfloat16* tBhi[2] = { smem + 2 * TILE_ELEMS, smem + 6 * TILE_ELEMS };
    __nv_bfloat16* tBlo[2] = { smem + 3 * TILE_ELEMS, smem + 7 * TILE_ELEMS };

    int tid  = threadIdx.x;
    int lane = tid & 31;
    int wid  = tid >> 5;
    int wm   = (wid & 1) * 64;
    int wn   = (wid >> 1) * 32;

    float c[4][4][4];
#pragma unroll
    for (int i = 0; i < 4; i++)
#pragma unroll
        for (int j = 0; j < 4; j++)
#pragma unroll
            for (int r = 0; r < 4; r++) c[i][j][r] = 0.f;

    const int T = K >> 5;

    int lrow[4], lcol[4];
#pragma unroll
    for (int j = 0; j < 4; j++) {
        int u = tid + j * 256;
        lrow[j] = u >> 3;
        lcol[j] = (u & 7) * 4;
    }

    float4 va[4], vb[4];
#pragma unroll
    for (int j = 0; j < 4; j++) {
        va[j] = *(const float4*)(A + (size_t)(m0 + lrow[j]) * K + lcol[j]);
        vb[j] = *(const float4*)(B + (size_t)(n0 + lrow[j]) * K + lcol[j]);
    }
#pragma unroll
    for (int j = 0; j < 4; j++) {
        uint2 h, l;
        int off = lrow[j] * SAST + lcol[j];
        split4(va[j], h, l);
        *(uint2*)(tAhi[0] + off) = h; *(uint2*)(tAlo[0] + off) = l;
        split4(vb[j], h, l);
        *(uint2*)(tBhi[0] + off) = h; *(uint2*)(tBlo[0] + off) = l;
    }
    __syncthreads();

    for (int cc = 0; cc < T; ++cc) {
        int p = cc & 1;

        if (cc + 1 < T) {
            int k0 = (cc + 1) << 5;
#pragma unroll
            for (int j = 0; j < 4; j++) {
                va[j] = *(const float4*)(A + (size_t)(m0 + lrow[j]) * K + k0 + lcol[j]);
                vb[j] = *(const float4*)(B + (size_t)(n0 + lrow[j]) * K + k0 + lcol[j]);
            }
        }

        uint32_t bAhi = smem_u32(tAhi[p]);
        uint32_t bAlo = smem_u32(tAlo[p]);
        uint32_t bBhi = smem_u32(tBhi[p]);
        uint32_t bBlo = smem_u32(tBlo[p]);
#pragma unroll
        for (int kk = 0; kk < 32; kk += 16) {
            uint32_t ah[4][4], bh[4][2], bl[4][2];
            uint32_t aoff = ((wm + (lane & 15)) * SAST + kk + ((lane >> 4) * 8)) * 2;
            uint32_t boff4 = ((wn + ((lane >> 4) << 3) + (lane & 7)) * SAST
                              + kk + (((lane >> 3) & 1) << 3)) * 2;
#pragma unroll
            for (int ma = 0; ma < 4; ma++)
                LDSM_X4(ah[ma][0], ah[ma][1], ah[ma][2], ah[ma][3],
                        bAhi + aoff + ma * (16 * SAST * 2));
#pragma unroll
            for (int nb2 = 0; nb2 < 2; nb2++)
                LDSM_X4(bh[2 * nb2][0], bh[2 * nb2][1],
                        bh[2 * nb2 + 1][0], bh[2 * nb2 + 1][1],
                        bBhi + boff4 + nb2 * (16 * SAST * 2));
#pragma unroll
            for (int ma = 0; ma < 4; ma++)
#pragma unroll
                for (int nb = 0; nb < 4; nb++)
                    MMA_BF16(c[ma][nb][0], c[ma][nb][1], c[ma][nb][2], c[ma][nb][3],
                             ah[ma][0], ah[ma][1], ah[ma][2], ah[ma][3],
                             bh[nb][0], bh[nb][1]);
#pragma unroll
            for (int nb2 = 0; nb2 < 2; nb2++)
                LDSM_X4(bl[2 * nb2][0], bl[2 * nb2][1],
                        bl[2 * nb2 + 1][0], bl[2 * nb2 + 1][1],
                        bBlo + boff4 + nb2 * (16 * SAST * 2));
#pragma unroll
            for (int nb = 0; nb < 4; nb++) {
#pragma unroll
                for (int ma = 0; ma < 4; ma++)
                    MMA_BF16(c[ma][nb][0], c[ma][nb][1], c[ma][nb][2], c[ma][nb][3],
                             ah[ma][0], ah[ma][1], ah[ma][2], ah[ma][3],
                             bl[nb][0], bl[nb][1]);
            }
#pragma unroll
            for (int ma = 0; ma < 4; ma++) {
                uint32_t al0, al1, al2, al3;
                LDSM_X4(al0, al1, al2, al3, bAlo + aoff + ma * (16 * SAST * 2));
#pragma unroll
                for (int nb = 0; nb < 4; nb++)
                    MMA_BF16(c[ma][nb][0], c[ma][nb][1], c[ma][nb][2], c[ma][nb][3],
                             al0, al1, al2, al3, bh[nb][0], bh[nb][1]);
            }
        }

        if (cc + 1 < T) {
            int q = p ^ 1;
#pragma unroll
            for (int j = 0; j < 4; j++) {
                uint2 h, l;
                int off = lrow[j] * SAST + lcol[j];
                split4(va[j], h, l);
                *(uint2*)(tAhi[q] + off) = h; *(uint2*)(tAlo[q] + off) = l;
                split4(vb[j], h, l);
                *(uint2*)(tBhi[q] + off) = h; *(uint2*)(tBlo[q] + off) = l;
            }
        }
        __syncthreads();
    }

#pragma unroll
    for (int ma = 0; ma < 4; ma++) {
        int mrow = m0 + wm + ma * 16 + (lane >> 2);
#pragma unroll
        for (int nb = 0; nb < 4; nb++) {
            int ncol = n0 + wn + nb * 8 + (lane & 3) * 2;
            float b0 = 0.f, b1 = 0.f;
            if (bias) { b0 = bias[ncol]; b1 = bias[ncol + 1]; }
            float v00 = c[ma][nb][0] + b0, v01 = c[ma][nb][1] + b1;
            float v10 = c[ma][nb][2] + b0, v11 = c[ma][nb][3] + b1;
            if (relu) {
                v00 = fmaxf(v00, 0.f); v01 = fmaxf(v01, 0.f);
                v10 = fmaxf(v10, 0.f); v11 = fmaxf(v11, 0.f);
            }
            *(float2*)(C + (size_t)mrow * N + ncol)       = make_float2(v00, v01);
            *(float2*)(C + (size_t)(mrow + 8) * N + ncol) = make_float2(v10, v11);
        }
    }
}

// plain GEMM (identical binary behavior to R13)
__global__ __launch_bounds__(256)
void gemm_f32(const float* __restrict__ A, const float* __restrict__ B,
              const float* __restrict__ bias, float* __restrict__ C,
              int M, int N, int K, int relu)
{
    extern __shared__ char smem_raw[];
    gemm_body(A, B, bias, C, M, N, K, relu,
              blockIdx.x * 128, blockIdx.y * 128, smem_raw);
}

// QKV GEMM: blockIdx.z selects weight/bias/output plane ONCE (scalar select,
// no indexed pointer arrays — the R14 failure mode).
__global__ __launch_bounds__(256)
void gemm_qkv(const float* __restrict__ A,
              const float* __restrict__ Bq, const float* __restrict__ Bk,
              const float* __restrict__ Bv,
              const float* __restrict__ bq, const float* __restrict__ bk,
              const float* __restrict__ bv,
              float* __restrict__ Cbase)
{
    extern __shared__ char smem_raw[];
    int z = blockIdx.z;
    const float* B    = (z == 0) ? Bq : ((z == 1) ? Bk : Bv);
    const float* bias = (z == 0) ? bq : ((z == 1) ? bk : bv);
    float* C = Cbase + (size_t)z * MM * DD;
    gemm_body(A, B, bias, C, MM, DD, DD, 0,
              blockIdx.x * 128, blockIdx.y * 128, smem_raw);
}

// ---------------- fused flash attention (R13 proven 64-row version) ---------
#define FST 72
#define FSMEM_BYTES (6 * 64 * FST * 2)   // 55296 B

__global__ __launch_bounds__(128)
void flash_attn(const float* __restrict__ q, const float* __restrict__ k,
                const float* __restrict__ v, float* __restrict__ o_out)
{
    extern __shared__ __nv_bfloat16 fsm[];
    __nv_bfloat16* Qh = fsm;
    __nv_bfloat16* Ql = fsm + 1 * 64 * FST;
    __nv_bfloat16* Kh = fsm + 2 * 64 * FST;
    __nv_bfloat16* Kl = fsm + 3 * 64 * FST;
    __nv_bfloat16* Vh = fsm + 4 * 64 * FST;
    __nv_bfloat16* Vl = fsm + 5 * 64 * FST;

    int tid = threadIdx.x, lane = tid & 31, w = tid >> 5;
    int i0 = blockIdx.x * 64;
    int bh = blockIdx.y;
    int b = bh >> 4, h = bh & 15;

    const float* qb = q + (size_t)b * SS * DD + h * DKK;
    const float* kb = k + (size_t)b * SS * DD + h * DKK;
    const float* vb = v + (size_t)b * SS * DD + h * DKK;

#pragma unroll
    for (int j = 0; j < 8; j++) {
        int u = tid + j * 128;
        int r = u >> 4, c = (u & 15) * 4;
        float4 t = *(const float4*)(qb + (size_t)(i0 + r) * DD + c);
        t.x *= 0.125f; t.y *= 0.125f; t.z *= 0.125f; t.w *= 0.125f;
        uint2 hi, lo; split4(t, hi, lo);
        *(uint2*)(Qh + r * FST + c) = hi;
        *(uint2*)(Ql + r * FST + c) = lo;
    }
    __syncthreads();

    uint32_t qh[4][4], ql[4][4];
    {
        uint32_t bQh = smem_u32(Qh), bQl = smem_u32(Ql);
#pragma unroll
        for (int kc = 0; kc < 4; kc++) {
            uint32_t off = ((w * 16 + (lane & 15)) * FST + kc * 16 + (lane >> 4) * 8) * 2;
            LDSM_X4(qh[kc][0], qh[kc][1], qh[kc][2], qh[kc][3], bQh + off);
            LDSM_X4(ql[kc][0], ql[kc][1], ql[kc][2], ql[kc][3], bQl + off);
        }
    }

    float o[8][4];
#pragma unroll
    for (int nb = 0; nb < 8; nb++)
#pragma unroll
        for (int r = 0; r < 4; r++) o[nb][r] = 0.f;
    float m0 = -1e30f, m1 = -1e30f, l0 = 0.f, l1 = 0.f;

    int row0 = i0 + w * 16 + (lane >> 2);
    int row1 = row0 + 8;

    for (int j0 = 0; j0 <= i0; j0 += 64) {
        __syncthreads();
#pragma unroll
        for (int j = 0; j < 8; j++) {
            int u = tid + j * 128;
            int r = u >> 4, c = (u & 15) * 4;
            uint2 hi, lo;
            float4 tk = *(const float4*)(kb + (size_t)(j0 + r) * DD + c);
            split4(tk, hi, lo);
            *(uint2*)(Kh + r * FST + c) = hi;
            *(uint2*)(Kl + r * FST + c) = lo;
            float4 tv = *(const float4*)(vb + (size_t)(j0 + r) * DD + c);
            split4(tv, hi, lo);
            *(uint2*)(Vh + r * FST + c) = hi;
            *(uint2*)(Vl + r * FST + c) = lo;
        }
        __syncthreads();

        float s[8][4];
#pragma unroll
        for (int nb = 0; nb < 8; nb++)
#pragma unroll
            for (int r = 0; r < 4; r++) s[nb][r] = 0.f;
        {
            uint32_t bKh = smem_u32(Kh), bKl = smem_u32(Kl);
#pragma unroll
            for (int kc = 0; kc < 4; kc++) {
#pragma unroll
                for (int nb2 = 0; nb2 < 4; nb2++) {
                    int e = 2 * nb2, od = 2 * nb2 + 1;
                    uint32_t off4 = ((nb2 * 16 + ((lane >> 4) << 3) + (lane & 7)) * FST
                                     + kc * 16 + (((lane >> 3) & 1) << 3)) * 2;
                    uint32_t h0, h1, h2, h3, g0, g1, g2, g3;
                    LDSM_X4(h0, h1, h2, h3, bKh + off4);
                    LDSM_X4(g0, g1, g2, g3, bKl + off4);
                    MMA_BF16(s[e][0], s[e][1], s[e][2], s[e][3],
                             qh[kc][0], qh[kc][1], qh[kc][2], qh[kc][3], h0, h1);
                    MMA_BF16(s[e][0], s[e][1], s[e][2], s[e][3],
                             qh[kc][0], qh[kc][1], qh[kc][2], qh[kc][3], g0, g1);
                    MMA_BF16(s[e][0], s[e][1], s[e][2], s[e][3],
                             ql[kc][0], ql[kc][1], ql[kc][2], ql[kc][3], h0, h1);
                    MMA_BF16(s[od][0], s[od][1], s[od][2], s[od][3],
                             qh[kc][0], qh[kc][1], qh[kc][2], qh[kc][3], h2, h3);
                    MMA_BF16(s[od][0], s[od][1], s[od][2], s[od][3],
                             qh[kc][0], qh[kc][1], qh[kc][2], qh[kc][3], g2, g3);
                    MMA_BF16(s[od][0], s[od][1], s[od][2], s[od][3],
                             ql[kc][0], ql[kc][1], ql[kc][2], ql[kc][3], h2, h3);
                }
            }
        }

        if (j0 == i0) {
#pragma unroll
            for (int nb = 0; nb < 8; nb++) {
                int col = j0 + nb * 8 + (lane & 3) * 2;
                if (col     > row0) s[nb][0] = -1e30f;
                if (col + 1 > row0) s[nb][1] = -1e30f;
                if (col     > row1) s[nb][2] = -1e30f;
                if (col + 1 > row1) s[nb][3] = -1e30f;
            }
        }

        float mx0 = -1e30f, mx1 = -1e30f;
#pragma unroll
        for (int nb = 0; nb < 8; nb++) {
            mx0 = fmaxf(mx0, fmaxf(s[nb][0], s[nb][1]));
            mx1 = fmaxf(mx1, fmaxf(s[nb][2], s[nb][3]));
        }
        mx0 = fmaxf(mx0, __shfl_xor_sync(~0u, mx0, 1));
        mx0 = fmaxf(mx0, __shfl_xor_sync(~0u, mx0, 2));
        mx1 = fmaxf(mx1, __shfl_xor_sync(~0u, mx1, 1));
        mx1 = fmaxf(mx1, __shfl_xor_sync(~0u, mx1, 2));
        float mn0 = fmaxf(m0, mx0), mn1 = fmaxf(m1, mx1);
        float a0 = __expf(m0 - mn0), a1 = __expf(m1 - mn1);

        float rs0 = 0.f, rs1 = 0.f;
        uint32_t pa[4][4];
#pragma unroll
        for (int kc = 0; kc < 4; kc++) {
            int e = 2 * kc, od = 2 * kc + 1;
            float p00 = __expf(s[e][0] - mn0),  p01 = __expf(s[e][1] - mn0);
            float p02 = __expf(s[e][2] - mn1),  p03 = __expf(s[e][3] - mn1);
            float p10 = __expf(s[od][0] - mn0), p11 = __expf(s[od][1] - mn0);
            float p12 = __expf(s[od][2] - mn1), p13 = __expf(s[od][3] - mn1);
            rs0 += p00 + p01 + p10 + p11;
            rs1 += p02 + p03 + p12 + p13;
            pa[kc][0] = pack_bf16x2(p00, p01);
            pa[kc][1] = pack_bf16x2(p02, p03);
            pa[kc][2] = pack_bf16x2(p10, p11);
            pa[kc][3] = pack_bf16x2(p12, p13);
        }
        rs0 += __shfl_xor_sync(~0u, rs0, 1);
        rs0 += __shfl_xor_sync(~0u, rs0, 2);
        rs1 += __shfl_xor_sync(~0u, rs1, 1);
        rs1 += __shfl_xor_sync(~0u, rs1, 2);
        l0 = l0 * a0 + rs0;
        l1 = l1 * a1 + rs1;
        m0 = mn0; m1 = mn1;
#pragma unroll
        for (int nb = 0; nb < 8; nb++) {
            o[nb][0] *= a0; o[nb][1] *= a0;
            o[nb][2] *= a1; o[nb][3] *= a1;
        }

        {
            uint32_t bVh = smem_u32(Vh), bVl = smem_u32(Vl);
#pragma unroll
            for (int kc = 0; kc < 4; kc++) {
#pragma unroll
                for (int nb2 = 0; nb2 < 4; nb2++) {
                    int e = 2 * nb2, od = 2 * nb2 + 1;
                    uint32_t offv = ((kc * 16 + (lane & 15)) * FST
                                     + nb2 * 16 + ((lane >> 4) << 3)) * 2;
                    uint32_t v0, v1, v2, v3, w0, w1, w2, w3;
                    LDSM_X4_T(v0, v1, v2, v3, bVh + offv);
                    LDSM_X4_T(w0, w1, w2, w3, bVl + offv);
                    MMA_BF16(o[e][0], o[e][1], o[e][2], o[e][3],
                             pa[kc][0], pa[kc][1], pa[kc][2], pa[kc][3], v0, v1);
                    MMA_BF16(o[e][0], o[e][1], o[e][2], o[e][3],
                             pa[kc][0], pa[kc][1], pa[kc][2], pa[kc][3], w0, w1);
                    MMA_BF16(o[od][0], o[od][1], o[od][2], o[od][3],
                             pa[kc][0], pa[kc][1], pa[kc][2], pa[kc][3], v2, v3);
                    MMA_BF16(o[od][0], o[od][1], o[od][2], o[od][3],
                             pa[kc][0], pa[kc][1], pa[kc][2], pa[kc][3], w2, w3);
                }
            }
        }
    }

    float inv0 = 1.f / l0, inv1 = 1.f / l1;
#pragma unroll
    for (int nb = 0; nb < 8; nb++) {
        int col = h * DKK + nb * 8 + (lane & 3) * 2;
        *(float2*)(o_out + (size_t)(b * SS + row0) * DD + col)
            = make_float2(o[nb][0] * inv0, o[nb][1] * inv0);
        *(float2*)(o_out + (size_t)(b * SS + row1) * DD + col)
            = make_float2(o[nb][2] * inv1, o[nb][3] * inv1);
    }
}

// ---------------- embedding + sinusoidal PE ---------------------------------
__global__ void embed_pe_kernel(const int* __restrict__ ids,
                                const float* __restrict__ emb,
                                float* __restrict__ x)
{
    int idx = blockIdx.x * 256 + threadIdx.x;
    int m = idx >> 10;
    int d = idx & 1023;
    int s = m & (SS - 1);
    int tok = ids[m];
    int twohalf = (d >> 1) << 1;
    float div = __expf(-(float)twohalf * (9.210340371976184f / (float)DD));
    float ang = (float)s * div;
    float pe  = (d & 1) ? cosf(ang) : sinf(ang);
    x[idx] = emb[(size_t)tok * DD + d] * 32.0f + pe;
}

// ---------------- fused residual + LayerNorm (shuffle reduction) ------------
__global__ __launch_bounds__(256)
void add_ln(const float* __restrict__ x, const float* __restrict__ y,
            const float* __restrict__ g, const float* __restrict__ bta,
            float* __restrict__ out)
{
    __shared__ float red[8];
    int row = blockIdx.x;
    int t = threadIdx.x, lane = t & 31, w = t >> 5;
    const float* xr = x + (size_t)row * DD;
    float v[4];
    float s = 0.f;
#pragma unroll
    for (int u = 0; u < 4; u++) {
        int idx = t + u * 256;
        float vv = xr[idx];
        if (y) vv += y[(size_t)row * DD + idx];
        v[u] = vv;
        s += vv;
    }
#pragma unroll
    for (int o = 16; o > 0; o >>= 1) s += __shfl_xor_sync(~0u, s, o);
    if (lane == 0) red[w] = s;
    __syncthreads();
    float tot = red[0];
#pragma unroll
    for (int q = 1; q < 8; q++) tot += red[q];
    float mean = tot * (1.f / DD);
    __syncthreads();

    float s2 = 0.f;
#pragma unroll
    for (int u = 0; u < 4; u++) { float d = v[u] - mean; s2 += d * d; }
#pragma unroll
    for (int o = 16; o > 0; o >>= 1) s2 += __shfl_xor_sync(~0u, s2, o);
    if (lane == 0) red[w] = s2;
    __syncthreads();
    float tot2 = red[0];
#pragma unroll
    for (int q = 1; q < 8; q++) tot2 += red[q];
    float rstd = rsqrtf(tot2 * (1.f / DD) + LNEPS);

    float* orow = out + (size_t)row * DD;
#pragma unroll
    for (int u = 0; u < 4; u++) {
        int idx = t + u * 256;
        orow[idx] = (v[u] - mean) * rstd * g[idx] + bta[idx];
    }
}

// ---------------- host orchestration ----------------------------------------
extern "C" void kernel_launch(void* const* d_in, const int* in_sizes, int n_in,
                              void* d_out, int out_size)
{
    (void)in_sizes; (void)n_in; (void)out_size;
    const int*   ids    = (const int*)  d_in[0];
    const float* embedw = (const float*)d_in[1];
    const float* Wq     = (const float*)d_in[2];
    const float* bq     = (const float*)d_in[3];
    const float* Wk     = (const float*)d_in[4];
    const float* bk     = (const float*)d_in[5];
    const float* Wv     = (const float*)d_in[6];
    const float* bv     = (const float*)d_in[7];
    const float* Wo     = (const float*)d_in[8];
    const float* bo     = (const float*)d_in[9];
    const float* ln1_g  = (const float*)d_in[10];
    const float* ln1_b  = (const float*)d_in[11];
    const float* W1     = (const float*)d_in[12];
    const float* b1     = (const float*)d_in[13];
    const float* W2     = (const float*)d_in[14];
    const float* b2     = (const float*)d_in[15];
    const float* ln2_g  = (const float*)d_in[16];
    const float* ln2_b  = (const float*)d_in[17];
    const float* lnf_g  = (const float*)d_in[18];
    const float* lnf_b  = (const float*)d_in[19];
    const float* head_w = (const float*)d_in[20];
    float* out = (float*)d_out;

    float *x, *qkv, *ao, *y, *ff;
    cudaGetSymbolAddress((void**)&x,   g_x);
    cudaGetSymbolAddress((void**)&qkv, g_qkv);
    cudaGetSymbolAddress((void**)&ao,  g_ao);
    cudaGetSymbolAddress((void**)&y,   g_y);
    cudaGetSymbolAddress((void**)&ff,  g_ff);
    float* qp = qkv;
    float* kp = qkv + (size_t)MM * DD;
    float* vp = qkv + (size_t)2 * MM * DD;

    cudaFuncSetAttribute(gemm_f32, cudaFuncAttributeMaxDynamicSharedMemorySize,
                         GSMEM_BYTES);
    cudaFuncSetAttribute(gemm_qkv, cudaFuncAttributeMaxDynamicSharedMemorySize,
                         GSMEM_BYTES);
    cudaFuncSetAttribute(flash_attn, cudaFuncAttributeMaxDynamicSharedMemorySize,
                         FSMEM_BYTES);

    auto gemm = [&](const float* A, const float* B, const float* bias,
                    float* C, int M, int N, int K, int relu) {
        gemm_f32<<<dim3(M / 128, N / 128), 256, GSMEM_BYTES>>>(
            A, B, bias, C, M, N, K, relu);
    };

    embed_pe_kernel<<<(MM * DD) / 256, 256>>>(ids, embedw, x);

    dim3 gFA(SS / 64, BB * HH);
    dim3 gQKV(MM / 128, DD / 128, 3);   // 16 x 8 x 3 = 384 CTAs

    for (int l = 0; l < LL; l++) {
        const float* wq = Wq + (size_t)l * DD * DD;
        const float* wk = Wk + (size_t)l * DD * DD;
        const float* wv = Wv + (size_t)l * DD * DD;
        const float* wo = Wo + (size_t)l * DD * DD;
        const float* w1 = W1 + (size_t)l * FF * DD;
        const float* w2 = W2 + (size_t)l * DD * FF;

        gemm_qkv<<<gQKV, 256, GSMEM_BYTES>>>(
            x, wq, wk, wv, bq + l * DD, bk + l * DD, bv + l * DD, qkv);

        flash_attn<<<gFA, 128, FSMEM_BYTES>>>(qp, kp, vp, ao);

        gemm(ao, wo, bo + l * DD, y, MM, DD, DD, 0);
        add_ln<<<MM, 256>>>(x, y, ln1_g + l * DD, ln1_b + l * DD, x);

        gemm(x, w1, b1 + l * FF, ff, MM, FF, DD, 1);
        gemm(ff, w2, b2 + l * DD, y, MM, DD, FF, 0);
        add_ln<<<MM, 256>>>(x, y, ln2_g + l * DD, ln2_b + l * DD, x);
    }

    add_ln<<<MM, 256>>>(x, (const float*)nullptr, lnf_g, lnf_b, x);
    gemm(x, head_w, (const float*)nullptr, out, MM, VV, DD, 0);
}

// round 17
// speedup vs baseline: 1.2721x; 1.2721x over previous
#include <cuda_runtime.h>
#include <cuda_bf16.h>
#include <cuda_fp16.h>
#include <math.h>
#include <stdint.h>

// ---------------- problem constants ----------------------------------------
#define BB   2
#define SS   1024
#define DD   1024
#define HH   16
#define DKK  64
#define FF   4096
#define LL   4
#define VV   32000
#define MM   (BB*SS)
#define LNEPS 1e-5f

// ---------------- device scratch (no allocation allowed) -------------------
__device__ float g_x [MM*DD];
__device__ float g_q [MM*DD];
__device__ float g_k [MM*DD];
__device__ float g_v [MM*DD];
__device__ float g_ao[MM*DD];
__device__ float g_y [MM*DD];
__device__ float g_ff[MM*FF];

// ---------------- helpers ---------------------------------------------------
__device__ __forceinline__ uint32_t smem_u32(const void* p) {
    uint32_t a;
    asm("{ .reg .u64 t; cvta.to.shared.u64 t, %1; cvt.u32.u64 %0, t; }"
        : "=r"(a) : "l"(p));
    return a;
}
#define LDSM_X4(r0, r1, r2, r3, addr) \
    asm volatile("ldmatrix.sync.aligned.m8n8.x4.shared.b16 {%0,%1,%2,%3}, [%4];" \
                 : "=r"(r0), "=r"(r1), "=r"(r2), "=r"(r3) : "r"(addr))
#define LDSM_X4_T(r0, r1, r2, r3, addr) \
    asm volatile("ldmatrix.sync.aligned.m8n8.x4.trans.shared.b16 {%0,%1,%2,%3}, [%4];" \
                 : "=r"(r0), "=r"(r1), "=r"(r2), "=r"(r3) : "r"(addr))
#define MMA_BF16(c0, c1, c2, c3, a0, a1, a2, a3, b0, b1) \
    asm volatile("mma.sync.aligned.m16n8k16.row.col.f32.bf16.bf16.f32 " \
                 "{%0,%1,%2,%3}, {%4,%5,%6,%7}, {%8,%9}, {%0,%1,%2,%3};" \
                 : "+f"(c0), "+f"(c1), "+f"(c2), "+f"(c3) \
                 : "r"(a0), "r"(a1), "r"(a2), "r"(a3), "r"(b0), "r"(b1))
#define MMA_F16(c0, c1, c2, c3, a0, a1, a2, a3, b0, b1) \
    asm volatile("mma.sync.aligned.m16n8k16.row.col.f32.f16.f16.f32 " \
                 "{%0,%1,%2,%3}, {%4,%5,%6,%7}, {%8,%9}, {%0,%1,%2,%3};" \
                 : "+f"(c0), "+f"(c1), "+f"(c2), "+f"(c3) \
                 : "r"(a0), "r"(a1), "r"(a2), "r"(a3), "r"(b0), "r"(b1))

// split float4 -> packed hi-bf16x4 and lo-bf16x4 (flash attention)
__device__ __forceinline__ void split4(float4 v, uint2& hi, uint2& lo) {
    uint32_t h0 = (uint32_t)__bfloat16_as_ushort(__float2bfloat16(v.x));
    uint32_t h1 = (uint32_t)__bfloat16_as_ushort(__float2bfloat16(v.y));
    uint32_t h2 = (uint32_t)__bfloat16_as_ushort(__float2bfloat16(v.z));
    uint32_t h3 = (uint32_t)__bfloat16_as_ushort(__float2bfloat16(v.w));
    hi.x = h0 | (h1 << 16);
    hi.y = h2 | (h3 << 16);
    float l0 = v.x - __uint_as_float(h0 << 16);
    float l1 = v.y - __uint_as_float(h1 << 16);
    float l2 = v.z - __uint_as_float(h2 << 16);
    float l3 = v.w - __uint_as_float(h3 << 16);
    uint32_t q0 = (uint32_t)__bfloat16_as_ushort(__float2bfloat16(l0));
    uint32_t q1 = (uint32_t)__bfloat16_as_ushort(__float2bfloat16(l1));
    uint32_t q2 = (uint32_t)__bfloat16_as_ushort(__float2bfloat16(l2));
    uint32_t q3 = (uint32_t)__bfloat16_as_ushort(__float2bfloat16(l3));
    lo.x = q0 | (q1 << 16);
    lo.y = q2 | (q3 << 16);
}

// fp16 splits for the GEMM (11-bit mantissa: residue ~2^-12)
__device__ __forceinline__ void split4h(float4 v, uint2& hi, uint2& lo) {
    __half h0 = __float2half_rn(v.x), h1 = __float2half_rn(v.y);
    __half h2 = __float2half_rn(v.z), h3 = __float2half_rn(v.w);
    hi.x = (uint32_t)__half_as_ushort(h0) | ((uint32_t)__half_as_ushort(h1) << 16);
    hi.y = (uint32_t)__half_as_ushort(h2) | ((uint32_t)__half_as_ushort(h3) << 16);
    __half l0 = __float2half_rn(v.x - __half2float(h0));
    __half l1 = __float2half_rn(v.y - __half2float(h1));
    __half l2 = __float2half_rn(v.z - __half2float(h2));
    __half l3 = __float2half_rn(v.w - __half2float(h3));
    lo.x = (uint32_t)__half_as_ushort(l0) | ((uint32_t)__half_as_ushort(l1) << 16);
    lo.y = (uint32_t)__half_as_ushort(l2) | ((uint32_t)__half_as_ushort(l3) << 16);
}
__device__ __forceinline__ void split4h_hi(float4 v, uint2& hi) {
    __half h0 = __float2half_rn(v.x), h1 = __float2half_rn(v.y);
    __half h2 = __float2half_rn(v.z), h3 = __float2half_rn(v.w);
    hi.x = (uint32_t)__half_as_ushort(h0) | ((uint32_t)__half_as_ushort(h1) << 16);
    hi.y = (uint32_t)__half_as_ushort(h2) | ((uint32_t)__half_as_ushort(h3) << 16);
}

__device__ __forceinline__ uint32_t pack_bf16x2(float a, float b) {
    uint32_t ua = (uint32_t)__bfloat16_as_ushort(__float2bfloat16(a));
    uint32_t ub = (uint32_t)__bfloat16_as_ushort(__float2bfloat16(b));
    return ua | (ub << 16);
}

// ---------------- HMMA GEMM: fp16 2-pass split (Ah*Bh + Ah*Bl) --------------
// CTA 128x128, 256 threads = 8 warps of 64x32, BK=32, double buffered.
// A stored hi-only (A-lo term dropped: fp16 residue 2^-12 makes it negligible
// vs the 1e-3 budget); B stored hi+lo. 32 MMAs/chunk vs 48 in the bf16 3-pass.
#define SAST 40
#define TILE_ELEMS (128 * SAST)
#define GSMEM_BYTES (6 * TILE_ELEMS * 2)   // 61440 B (3 tiles x 2 buffers)

__global__ __launch_bounds__(256)
void gemm_f32(const float* __restrict__ A, const float* __restrict__ B,
              const float* __restrict__ bias, float* __restrict__ C,
              int M, int N, int K, int relu)
{
    extern __shared__ __half smem[];
    __half* tAhi[2] = { smem,                  smem + 3 * TILE_ELEMS };
    __half* tBhi[2] = { smem + 1 * TILE_ELEMS, smem + 4 * TILE_ELEMS };
    __half* tBlo[2] = { smem + 2 * TILE_ELEMS, smem + 5 * TILE_ELEMS };

    int tid  = threadIdx.x;
    int lane = tid & 31;
    int wid  = tid >> 5;
    int wm   = (wid & 1) * 64;
    int wn   = (wid >> 1) * 32;
    int m0   = blockIdx.x * 128;
    int n0   = blockIdx.y * 128;

    float c[4][4][4];
#pragma unroll
    for (int i = 0; i < 4; i++)
#pragma unroll
        for (int j = 0; j < 4; j++)
#pragma unroll
            for (int r = 0; r < 4; r++) c[i][j][r] = 0.f;

    const int T = K >> 5;

    int lrow[4], lcol[4];
#pragma unroll
    for (int j = 0; j < 4; j++) {
        int u = tid + j * 256;
        lrow[j] = u >> 3;
        lcol[j] = (u & 7) * 4;
    }

    float4 va[4], vb[4];
#pragma unroll
    for (int j = 0; j < 4; j++) {
        va[j] = *(const float4*)(A + (size_t)(m0 + lrow[j]) * K + lcol[j]);
        vb[j] = *(const float4*)(B + (size_t)(n0 + lrow[j]) * K + lcol[j]);
    }
#pragma unroll
    for (int j = 0; j < 4; j++) {
        uint2 h, l;
        int off = lrow[j] * SAST + lcol[j];
        split4h_hi(va[j], h);
        *(uint2*)(tAhi[0] + off) = h;
        split4h(vb[j], h, l);
        *(uint2*)(tBhi[0] + off) = h; *(uint2*)(tBlo[0] + off) = l;
    }
    __syncthreads();

    for (int cc = 0; cc < T; ++cc) {
        int p = cc & 1;

        if (cc + 1 < T) {
            int k0 = (cc + 1) << 5;
#pragma unroll
            for (int j = 0; j < 4; j++) {
                va[j] = *(const float4*)(A + (size_t)(m0 + lrow[j]) * K + k0 + lcol[j]);
                vb[j] = *(const float4*)(B + (size_t)(n0 + lrow[j]) * K + k0 + lcol[j]);
            }
        }

        uint32_t bAhi = smem_u32(tAhi[p]);
        uint32_t bBhi = smem_u32(tBhi[p]);
        uint32_t bBlo = smem_u32(tBlo[p]);
#pragma unroll
        for (int kk = 0; kk < 32; kk += 16) {
            uint32_t ah[4][4], bh[4][2], bl[4][2];
            uint32_t aoff = ((wm + (lane & 15)) * SAST + kk + ((lane >> 4) * 8)) * 2;
            uint32_t boff4 = ((wn + ((lane >> 4) << 3) + (lane & 7)) * SAST
                              + kk + (((lane >> 3) & 1) << 3)) * 2;
#pragma unroll
            for (int ma = 0; ma < 4; ma++)
                LDSM_X4(ah[ma][0], ah[ma][1], ah[ma][2], ah[ma][3],
                        bAhi + aoff + ma * (16 * SAST * 2));
#pragma unroll
            for (int nb2 = 0; nb2 < 2; nb2++)
                LDSM_X4(bh[2 * nb2][0], bh[2 * nb2][1],
                        bh[2 * nb2 + 1][0], bh[2 * nb2 + 1][1],
                        bBhi + boff4 + nb2 * (16 * SAST * 2));
            // pass 1: Ah * Bh
#pragma unroll
            for (int ma = 0; ma < 4; ma++)
#pragma unroll
                for (int nb = 0; nb < 4; nb++)
                    MMA_F16(c[ma][nb][0], c[ma][nb][1], c[ma][nb][2], c[ma][nb][3],
                            ah[ma][0], ah[ma][1], ah[ma][2], ah[ma][3],
                            bh[nb][0], bh[nb][1]);
            // pass 2: Ah * Bl
#pragma unroll
            for (int nb2 = 0; nb2 < 2; nb2++)
                LDSM_X4(bl[2 * nb2][0], bl[2 * nb2][1],
                        bl[2 * nb2 + 1][0], bl[2 * nb2 + 1][1],
                        bBlo + boff4 + nb2 * (16 * SAST * 2));
#pragma unroll
            for (int nb = 0; nb < 4; nb++) {
#pragma unroll
                for (int ma = 0; ma < 4; ma++)
                    MMA_F16(c[ma][nb][0], c[ma][nb][1], c[ma][nb][2], c[ma][nb][3],
                            ah[ma][0], ah[ma][1], ah[ma][2], ah[ma][3],
                            bl[nb][0], bl[nb][1]);
            }
        }

        if (cc + 1 < T) {
            int q = p ^ 1;
#pragma unroll
            for (int j = 0; j < 4; j++) {
                uint2 h, l;
                int off = lrow[j] * SAST + lcol[j];
                split4h_hi(va[j], h);
                *(uint2*)(tAhi[q] + off) = h;
                split4h(vb[j], h, l);
                *(uint2*)(tBhi[q] + off) = h; *(uint2*)(tBlo[q] + off) = l;
            }
        }
        __syncthreads();
    }

#pragma unroll
    for (int ma = 0; ma < 4; ma++) {
        int mrow = m0 + wm + ma * 16 + (lane >> 2);
#pragma unroll
        for (int nb = 0; nb < 4; nb++) {
            int ncol = n0 + wn + nb * 8 + (lane & 3) * 2;
            float b0 = 0.f, b1 = 0.f;
            if (bias) { b0 = bias[ncol]; b1 = bias[ncol + 1]; }
            float v00 = c[ma][nb][0] + b0, v01 = c[ma][nb][1] + b1;
            float v10 = c[ma][nb][2] + b0, v11 = c[ma][nb][3] + b1;
            if (relu) {
                v00 = fmaxf(v00, 0.f); v01 = fmaxf(v01, 0.f);
                v10 = fmaxf(v10, 0.f); v11 = fmaxf(v11, 0.f);
            }
            *(float2*)(C + (size_t)mrow * N + ncol)       = make_float2(v00, v01);
            *(float2*)(C + (size_t)(mrow + 8) * N + ncol) = make_float2(v10, v11);
        }
    }
}

// ---------------- fused flash attention (exact R13) -------------------------
#define FST 72
#define FSMEM_BYTES (6 * 64 * FST * 2)   // 55296 B

__global__ __launch_bounds__(128)
void flash_attn(const float* __restrict__ q, const float* __restrict__ k,
                const float* __restrict__ v, float* __restrict__ o_out)
{
    extern __shared__ __nv_bfloat16 fsm[];
    __nv_bfloat16* Qh = fsm;
    __nv_bfloat16* Ql = fsm + 1 * 64 * FST;
    __nv_bfloat16* Kh = fsm + 2 * 64 * FST;
    __nv_bfloat16* Kl = fsm + 3 * 64 * FST;
    __nv_bfloat16* Vh = fsm + 4 * 64 * FST;
    __nv_bfloat16* Vl = fsm + 5 * 64 * FST;

    int tid = threadIdx.x, lane = tid & 31, w = tid >> 5;
    int i0 = blockIdx.x * 64;
    int bh = blockIdx.y;
    int b = bh >> 4, h = bh & 15;

    const float* qb = q + (size_t)b * SS * DD + h * DKK;
    const float* kb = k + (size_t)b * SS * DD + h * DKK;
    const float* vb = v + (size_t)b * SS * DD + h * DKK;

#pragma unroll
    for (int j = 0; j < 8; j++) {
        int u = tid + j * 128;
        int r = u >> 4, c = (u & 15) * 4;
        float4 t = *(const float4*)(qb + (size_t)(i0 + r) * DD + c);
        t.x *= 0.125f; t.y *= 0.125f; t.z *= 0.125f; t.w *= 0.125f;
        uint2 hi, lo; split4(t, hi, lo);
        *(uint2*)(Qh + r * FST + c) = hi;
        *(uint2*)(Ql + r * FST + c) = lo;
    }
    __syncthreads();

    uint32_t qh[4][4], ql[4][4];
    {
        uint32_t bQh = smem_u32(Qh), bQl = smem_u32(Ql);
#pragma unroll
        for (int kc = 0; kc < 4; kc++) {
            uint32_t off = ((w * 16 + (lane & 15)) * FST + kc * 16 + (lane >> 4) * 8) * 2;
            LDSM_X4(qh[kc][0], qh[kc][1], qh[kc][2], qh[kc][3], bQh + off);
            LDSM_X4(ql[kc][0], ql[kc][1], ql[kc][2], ql[kc][3], bQl + off);
        }
    }

    float o[8][4];
#pragma unroll
    for (int nb = 0; nb < 8; nb++)
#pragma unroll
        for (int r = 0; r < 4; r++) o[nb][r] = 0.f;
    float m0 = -1e30f, m1 = -1e30f, l0 = 0.f, l1 = 0.f;

    int row0 = i0 + w * 16 + (lane >> 2);
    int row1 = row0 + 8;

    for (int j0 = 0; j0 <= i0; j0 += 64) {
        __syncthreads();
#pragma unroll
        for (int j = 0; j < 8; j++) {
            int u = tid + j * 128;
            int r = u >> 4, c = (u & 15) * 4;
            uint2 hi, lo;
            float4 tk = *(const float4*)(kb + (size_t)(j0 + r) * DD + c);
            split4(tk, hi, lo);
            *(uint2*)(Kh + r * FST + c) = hi;
            *(uint2*)(Kl + r * FST + c) = lo;
            float4 tv = *(const float4*)(vb + (size_t)(j0 + r) * DD + c);
            split4(tv, hi, lo);
            *(uint2*)(Vh + r * FST + c) = hi;
            *(uint2*)(Vl + r * FST + c) = lo;
        }
        __syncthreads();

        float s[8][4];
#pragma unroll
        for (int nb = 0; nb < 8; nb++)
#pragma unroll
            for (int r = 0; r < 4; r++) s[nb][r] = 0.f;
        {
            uint32_t bKh = smem_u32(Kh), bKl = smem_u32(Kl);
#pragma unroll
            for (int kc = 0; kc < 4; kc++) {
#pragma unroll
                for (int nb2 = 0; nb2 < 4; nb2++) {
                    int e = 2 * nb2, od = 2 * nb2 + 1;
                    uint32_t off4 = ((nb2 * 16 + ((lane >> 4) << 3) + (lane & 7)) * FST
                                     + kc * 16 + (((lane >> 3) & 1) << 3)) * 2;
                    uint32_t h0, h1, h2, h3, g0, g1, g2, g3;
                    LDSM_X4(h0, h1, h2, h3, bKh + off4);
                    LDSM_X4(g0, g1, g2, g3, bKl + off4);
                    MMA_BF16(s[e][0], s[e][1], s[e][2], s[e][3],
                             qh[kc][0], qh[kc][1], qh[kc][2], qh[kc][3], h0, h1);
                    MMA_BF16(s[e][0], s[e][1], s[e][2], s[e][3],
                             qh[kc][0], qh[kc][1], qh[kc][2], qh[kc][3], g0, g1);
                    MMA_BF16(s[e][0], s[e][1], s[e][2], s[e][3],
                             ql[kc][0], ql[kc][1], ql[kc][2], ql[kc][3], h0, h1);
                    MMA_BF16(s[od][0], s[od][1], s[od][2], s[od][3],
                             qh[kc][0], qh[kc][1], qh[kc][2], qh[kc][3], h2, h3);
                    MMA_BF16(s[od][0], s[od][1], s[od][2], s[od][3],
                             qh[kc][0], qh[kc][1], qh[kc][2], qh[kc][3], g2, g3);
                    MMA_BF16(s[od][0], s[od][1], s[od][2], s[od][3],
                             ql[kc][0], ql[kc][1], ql[kc][2], ql[kc][3], h2, h3);
                }
            }
        }

        if (j0 == i0) {
#pragma unroll
            for (int nb = 0; nb < 8; nb++) {
                int col = j0 + nb * 8 + (lane & 3) * 2;
                if (col     > row0) s[nb][0] = -1e30f;
                if (col + 1 > row0) s[nb][1] = -1e30f;
                if (col     > row1) s[nb][2] = -1e30f;
                if (col + 1 > row1) s[nb][3] = -1e30f;
            }
        }

        float mx0 = -1e30f, mx1 = -1e30f;
#pragma unroll
        for (int nb = 0; nb < 8; nb++) {
            mx0 = fmaxf(mx0, fmaxf(s[nb][0], s[nb][1]));
            mx1 = fmaxf(mx1, fmaxf(s[nb][2], s[nb][3]));
        }
        mx0 = fmaxf(mx0, __shfl_xor_sync(~0u, mx0, 1));
        mx0 = fmaxf(mx0, __shfl_xor_sync(~0u, mx0, 2));
        mx1 = fmaxf(mx1, __shfl_xor_sync(~0u, mx1, 1));
        mx1 = fmaxf(mx1, __shfl_xor_sync(~0u, mx1, 2));
        float mn0 = fmaxf(m0, mx0), mn1 = fmaxf(m1, mx1);
        float a0 = __expf(m0 - mn0), a1 = __expf(m1 - mn1);

        float rs0 = 0.f, rs1 = 0.f;
        uint32_t pa[4][4];
#pragma unroll
        for (int kc = 0; kc < 4; kc++) {
            int e = 2 * kc, od = 2 * kc + 1;
            float p00 = __expf(s[e][0] - mn0),  p01 = __expf(s[e][1] - mn0);
            float p02 = __expf(s[e][2] - mn1),  p03 = __expf(s[e][3] - mn1);
            float p10 = __expf(s[od][0] - mn0), p11 = __expf(s[od][1] - mn0);
            float p12 = __expf(s[od][2] - mn1), p13 = __expf(s[od][3] - mn1);
            rs0 += p00 + p01 + p10 + p11;
            rs1 += p02 + p03 + p12 + p13;
            pa[kc][0] = pack_bf16x2(p00, p01);
            pa[kc][1] = pack_bf16x2(p02, p03);
            pa[kc][2] = pack_bf16x2(p10, p11);
            pa[kc][3] = pack_bf16x2(p12, p13);
        }
        rs0 += __shfl_xor_sync(~0u, rs0, 1);
        rs0 += __shfl_xor_sync(~0u, rs0, 2);
        rs1 += __shfl_xor_sync(~0u, rs1, 1);
        rs1 += __shfl_xor_sync(~0u, rs1, 2);
        l0 = l0 * a0 + rs0;
        l1 = l1 * a1 + rs1;
        m0 = mn0; m1 = mn1;
#pragma unroll
        for (int nb = 0; nb < 8; nb++) {
            o[nb][0] *= a0; o[nb][1] *= a0;
            o[nb][2] *= a1; o[nb][3] *= a1;
        }

        {
            uint32_t bVh = smem_u32(Vh), bVl = smem_u32(Vl);
#pragma unroll
            for (int kc = 0; kc < 4; kc++) {
#pragma unroll
                for (int nb2 = 0; nb2 < 4; nb2++) {
                    int e = 2 * nb2, od = 2 * nb2 + 1;
                    uint32_t offv = ((kc * 16 + (lane & 15)) * FST
                                     + nb2 * 16 + ((lane >> 4) << 3)) * 2;
                    uint32_t v0, v1, v2, v3, w0, w1, w2, w3;
                    LDSM_X4_T(v0, v1, v2, v3, bVh + offv);
                    LDSM_X4_T(w0, w1, w2, w3, bVl + offv);
                    MMA_BF16(o[e][0], o[e][1], o[e][2], o[e][3],
                             pa[kc][0], pa[kc][1], pa[kc][2], pa[kc][3], v0, v1);
                    MMA_BF16(o[e][0], o[e][1], o[e][2], o[e][3],
                             pa[kc][0], pa[kc][1], pa[kc][2], pa[kc][3], w0, w1);
                    MMA_BF16(o[od][0], o[od][1], o[od][2], o[od][3],
                             pa[kc][0], pa[kc][1], pa[kc][2], pa[kc][3], v2, v3);
                    MMA_BF16(o[od][0], o[od][1], o[od][2], o[od][3],
                             pa[kc][0], pa[kc][1], pa[kc][2], pa[kc][3], w2, w3);
                }
            }
        }
    }

    float inv0 = 1.f / l0, inv1 = 1.f / l1;
#pragma unroll
    for (int nb = 0; nb < 8; nb++) {
        int col = h * DKK + nb * 8 + (lane & 3) * 2;
        *(float2*)(o_out + (size_t)(b * SS + row0) * DD + col)
            = make_float2(o[nb][0] * inv0, o[nb][1] * inv0);
        *(float2*)(o_out + (size_t)(b * SS + row1) * DD + col)
            = make_float2(o[nb][2] * inv1, o[nb][3] * inv1);
    }
}

// ---------------- embedding + sinusoidal PE ---------------------------------
__global__ void embed_pe_kernel(const int* __restrict__ ids,
                                const float* __restrict__ emb,
                                float* __restrict__ x)
{
    int idx = blockIdx.x * 256 + threadIdx.x;
    int m = idx >> 10;
    int d = idx & 1023;
    int s = m & (SS - 1);
    int tok = ids[m];
    int twohalf = (d >> 1) << 1;
    float div = __expf(-(float)twohalf * (9.210340371976184f / (float)DD));
    float ang = (float)s * div;
    float pe  = (d & 1) ? cosf(ang) : sinf(ang);
    x[idx] = emb[(size_t)tok * DD + d] * 32.0f + pe;
}

// ---------------- fused residual + LayerNorm (shuffle reduction) ------------
__global__ __launch_bounds__(256)
void add_ln(const float* __restrict__ x, const float* __restrict__ y,
            const float* __restrict__ g, const float* __restrict__ bta,
            float* __restrict__ out)
{
    __shared__ float red[8];
    int row = blockIdx.x;
    int t = threadIdx.x, lane = t & 31, w = t >> 5;
    const float* xr = x + (size_t)row * DD;
    float v[4];
    float s = 0.f;
#pragma unroll
    for (int u = 0; u < 4; u++) {
        int idx = t + u * 256;
        float vv = xr[idx];
        if (y) vv += y[(size_t)row * DD + idx];
        v[u] = vv;
        s += vv;
    }
#pragma unroll
    for (int o = 16; o > 0; o >>= 1) s += __shfl_xor_sync(~0u, s, o);
    if (lane == 0) red[w] = s;
    __syncthreads();
    float tot = red[0];
#pragma unroll
    for (int q = 1; q < 8; q++) tot += red[q];
    float mean = tot * (1.f / DD);
    __syncthreads();

    float s2 = 0.f;
#pragma unroll
    for (int u = 0; u < 4; u++) { float d = v[u] - mean; s2 += d * d; }
#pragma unroll
    for (int o = 16; o > 0; o >>= 1) s2 += __shfl_xor_sync(~0u, s2, o);
    if (lane == 0) red[w] = s2;
    __syncthreads();
    float tot2 = red[0];
#pragma unroll
    for (int q = 1; q < 8; q++) tot2 += red[q];
    float rstd = rsqrtf(tot2 * (1.f / DD) + LNEPS);

    float* orow = out + (size_t)row * DD;
#pragma unroll
    for (int u = 0; u < 4; u++) {
        int idx = t + u * 256;
        orow[idx] = (v[u] - mean) * rstd * g[idx] + bta[idx];
    }
}

// ---------------- host orchestration ----------------------------------------
extern "C" void kernel_launch(void* const* d_in, const int* in_sizes, int n_in,
                              void* d_out, int out_size)
{
    (void)in_sizes; (void)n_in; (void)out_size;
    const int*   ids    = (const int*)  d_in[0];
    const float* embedw = (const float*)d_in[1];
    const float* Wq     = (const float*)d_in[2];
    const float* bq     = (const float*)d_in[3];
    const float* Wk     = (const float*)d_in[4];
    const float* bk     = (const float*)d_in[5];
    const float* Wv     = (const float*)d_in[6];
    const float* bv     = (const float*)d_in[7];
    const float* Wo     = (const float*)d_in[8];
    const float* bo     = (const float*)d_in[9];
    const float* ln1_g  = (const float*)d_in[10];
    const float* ln1_b  = (const float*)d_in[11];
    const float* W1     = (const float*)d_in[12];
    const float* b1     = (const float*)d_in[13];
    const float* W2     = (const float*)d_in[14];
    const float* b2     = (const float*)d_in[15];
    const float* ln2_g  = (const float*)d_in[16];
    const float* ln2_b  = (const float*)d_in[17];
    const float* lnf_g  = (const float*)d_in[18];
    const float* lnf_b  = (const float*)d_in[19];
    const float* head_w = (const float*)d_in[20];
    float* out = (float*)d_out;

    float *x, *q, *k, *v, *ao, *y, *ff;
    cudaGetSymbolAddress((void**)&x,  g_x);
    cudaGetSymbolAddress((void**)&q,  g_q);
    cudaGetSymbolAddress((void**)&k,  g_k);
    cudaGetSymbolAddress((void**)&v,  g_v);
    cudaGetSymbolAddress((void**)&ao, g_ao);
    cudaGetSymbolAddress((void**)&y,  g_y);
    cudaGetSymbolAddress((void**)&ff, g_ff);

    cudaFuncSetAttribute(gemm_f32, cudaFuncAttributeMaxDynamicSharedMemorySize,
                         GSMEM_BYTES);
    cudaFuncSetAttribute(flash_attn, cudaFuncAttributeMaxDynamicSharedMemorySize,
                         FSMEM_BYTES);

    auto gemm = [&](const float* A, const float* B, const float* bias,
                    float* C, int M, int N, int K, int relu) {
        gemm_f32<<<dim3(M / 128, N / 128), 256, GSMEM_BYTES>>>(
            A, B, bias, C, M, N, K, relu);
    };

    embed_pe_kernel<<<(MM * DD) / 256, 256>>>(ids, embedw, x);

    dim3 gFA(SS / 64, BB * HH);

    for (int l = 0; l < LL; l++) {
        const float* wq = Wq + (size_t)l * DD * DD;
        const float* wk = Wk + (size_t)l * DD * DD;
        const float* wv = Wv + (size_t)l * DD * DD;
        const float* wo = Wo + (size_t)l * DD * DD;
        const float* w1 = W1 + (size_t)l * FF * DD;
        const float* w2 = W2 + (size_t)l * DD * FF;

        gemm(x, wq, bq + l * DD, q, MM, DD, DD, 0);
        gemm(x, wk, bk + l * DD, k, MM, DD, DD, 0);
        gemm(x, wv, bv + l * DD, v, MM, DD, DD, 0);

        flash_attn<<<gFA, 128, FSMEM_BYTES>>>(q, k, v, ao);

        gemm(ao, wo, bo + l * DD, y, MM, DD, DD, 0);
        add_ln<<<MM, 256>>>(x, y, ln1_g + l * DD, ln1_b + l * DD, x);

        gemm(x, w1, b1 + l * FF, ff, MM, FF, DD, 1);
        gemm(ff, w2, b2 + l * DD, y, MM, DD, FF, 0);
        add_ln<<<MM, 256>>>(x, y, ln2_g + l * DD, ln2_b + l * DD, x);
    }

    add_ln<<<MM, 256>>>(x, (const float*)nullptr, lnf_g, lnf_b, x);
    gemm(x, head_w, (const float*)nullptr, out, MM, VV, DD, 0);
}